// round 1
// baseline (speedup 1.0000x reference)
#include <cuda_runtime.h>
#include <math.h>

#define N_NODES 50000
#define N_EDGES 800000
#define IN_F 128
#define OUT_F 128
#define BN_EPS 1e-5f

// ---------------- device scratch (no allocation allowed) ----------------
__device__ float g_agg[N_NODES * IN_F];     // scatter-sum of neighbor feats
__device__ float g_cnt[N_NODES];            // in-degree counts
__device__ float g_Wa[OUT_F * IN_F];        // W_fuse_x + alpha * (M @ W_in)
__device__ float g_Wb[OUT_F * IN_F];        // W_fuse_agg
__device__ float g_bias[OUT_F];             // b_fuse + alpha * (M @ b_in)
__device__ float g_pre[N_NODES * OUT_F];    // pre-BN output
__device__ float g_sum[OUT_F];
__device__ float g_sumsq[OUT_F];
__device__ float g_scale[OUT_F];
__device__ float g_shift[OUT_F];
__device__ int   g_is64;                    // edge_index dtype flag

// ---------------- K0: zero scratch ----------------
__global__ void zero_kernel() {
    int i = blockIdx.x * blockDim.x + threadIdx.x;
    int stride = gridDim.x * blockDim.x;
    for (int j = i; j < N_NODES * IN_F; j += stride) g_agg[j] = 0.f;
    for (int j = i; j < N_NODES; j += stride) g_cnt[j] = 0.f;
    if (i < OUT_F) { g_sum[i] = 0.f; g_sumsq[i] = 0.f; }
}

// ---------------- K0b: detect edge_index dtype (int64 vs int32) ----------------
__global__ void detect_kernel(const long long* __restrict__ ei) {
    if (threadIdx.x == 0 && blockIdx.x == 0) {
        int ok = 1;
        for (int i = 0; i < 1024; ++i) {
            long long v = ei[i];
            if (v < 0 || v >= (long long)N_NODES) { ok = 0; break; }
        }
        g_is64 = ok;
    }
}

// ---------------- K1: fold spectral circulant into weights ----------------
// k[d] = (1/128) [ wr0 + wr64*(-1)^d + sum_{f=1..63} 2(wr_f cos(2pi f d/128) - wi_f sin(2pi f d/128)) ]
// W_eff[t][i] = sum_s k[(t-s) mod 128] * W_in[s][i]
__global__ void precompute_kernel(const float* __restrict__ W_fuse,
                                  const float* __restrict__ b_fuse,
                                  const float* __restrict__ W_in,
                                  const float* __restrict__ b_in,
                                  const float* __restrict__ cw,
                                  const float* __restrict__ alpha_p) {
    __shared__ float k_sh[128];
    int t = blockIdx.x;        // output row 0..127
    int i = threadIdx.x;       // 0..127
    // every block recomputes k (cheap)
    {
        float acc = cw[0];
        acc += cw[128] * ((i & 1) ? -1.f : 1.f);
        for (int f = 1; f < 64; ++f) {
            float wr = cw[2 * f], wi = cw[2 * f + 1];
            int m = (f * i) & 127;                 // exact angle mod 2pi
            float theta = (float)m * (6.283185307179586f / 128.f);
            float s, c;
            sincosf(theta, &s, &c);
            acc += 2.f * (wr * c - wi * s);
        }
        k_sh[i] = acc * (1.f / 128.f);
    }
    __syncthreads();
    float alpha = *alpha_p;
    float w = 0.f;
    #pragma unroll 8
    for (int s = 0; s < 128; ++s) {
        w += k_sh[(t - s) & 127] * W_in[s * IN_F + i];   // coalesced over i
    }
    g_Wa[t * IN_F + i] = W_fuse[t * (2 * IN_F) + i] + alpha * w;
    g_Wb[t * IN_F + i] = W_fuse[t * (2 * IN_F) + IN_F + i];
    if (i == 0) {
        float b = 0.f;
        for (int s = 0; s < 128; ++s) b += k_sh[(t - s) & 127] * b_in[s];
        g_bias[t] = b_fuse[t] + alpha * b;
    }
}

// ---------------- K2: scatter-sum aggregation (warp per edge) ----------------
__global__ __launch_bounds__(256) void agg_kernel(const float* __restrict__ x,
                                                  const long long* __restrict__ ei) {
    int warp = (blockIdx.x * blockDim.x + threadIdx.x) >> 5;
    int lane = threadIdx.x & 31;
    if (warp >= N_EDGES) return;
    long long src, dst;
    if (g_is64) {
        src = ei[warp];                 // same addr across warp -> broadcast load
        dst = ei[N_EDGES + warp];
    } else {
        const int* ei32 = (const int*)ei;
        src = (long long)ei32[warp];
        dst = (long long)ei32[N_EDGES + warp];
    }
    const float4* xr = reinterpret_cast<const float4*>(x + (size_t)src * IN_F);
    float4 v = xr[lane];                // 32 lanes x 16B = full 512B row
    float4* ar = reinterpret_cast<float4*>(g_agg + (size_t)dst * IN_F) + lane;
    asm volatile("red.global.add.v4.f32 [%0], {%1, %2, %3, %4};"
                 :: "l"(ar), "f"(v.x), "f"(v.y), "f"(v.z), "f"(v.w) : "memory");
    if (lane == 0) atomicAdd(&g_cnt[dst], 1.f);
}

// ---------------- K3: fused GEMM  out = x@Wa^T + (agg/cnt)@Wb^T + bias ----------------
// + fused per-feature sum/sumsq accumulation for BatchNorm
#define BM 64
__global__ __launch_bounds__(256) void gemm_kernel(const float* __restrict__ x) {
    __shared__ float Xs[BM][36];        // [row][k], padded (row stride 144B, 16B-aligned)
    __shared__ float Ws[32][128];       // [k][col]
    __shared__ float rinv[BM];
    __shared__ float bsum[128];
    __shared__ float bsq[128];

    int tid = threadIdx.x;
    int row0 = blockIdx.x * BM;
    int tr = tid >> 4;                  // 0..15 -> rows tr*4..tr*4+3
    int tc = tid & 15;                  // 0..15 -> cols tc*8..tc*8+7

    if (tid < BM) {
        int r = row0 + tid;
        float c = (r < N_NODES) ? g_cnt[r] : 1.f;
        rinv[tid] = 1.f / fmaxf(c, 1.f);
    }
    if (tid < 128) { bsum[tid] = 0.f; bsq[tid] = 0.f; }

    float acc[4][8];
    #pragma unroll
    for (int a = 0; a < 4; ++a)
        #pragma unroll
        for (int b = 0; b < 8; ++b) acc[a][b] = 0.f;

    for (int half = 0; half < 2; ++half) {
        const float* src = half ? g_agg : x;
        const float* W = half ? g_Wb : g_Wa;
        for (int k0 = 0; k0 < 128; k0 += 32) {
            __syncthreads();
            // X tile: 64 rows x 32 k = 512 float4; 2 per thread
            #pragma unroll
            for (int l = 0; l < 2; ++l) {
                int idx = tid + l * 256;
                int r = idx >> 3, seg = idx & 7;
                int gr = row0 + r;
                if (gr >= N_NODES) gr = N_NODES - 1;
                float4 v = *reinterpret_cast<const float4*>(src + (size_t)gr * 128 + k0 + seg * 4);
                if (half) { float ri = rinv[r]; v.x *= ri; v.y *= ri; v.z *= ri; v.w *= ri; }
                *reinterpret_cast<float4*>(&Xs[r][seg * 4]) = v;
            }
            // W tile transposed: Ws[k][c] = W[c][k0+k]; 1024 float4 reads, 4 per thread
            #pragma unroll
            for (int l = 0; l < 4; ++l) {
                int idx = tid + l * 256;
                int c = idx >> 3, seg = idx & 7;
                float4 v = *reinterpret_cast<const float4*>(W + c * 128 + k0 + seg * 4);
                Ws[seg * 4 + 0][c] = v.x;
                Ws[seg * 4 + 1][c] = v.y;
                Ws[seg * 4 + 2][c] = v.z;
                Ws[seg * 4 + 3][c] = v.w;
            }
            __syncthreads();
            #pragma unroll
            for (int k = 0; k < 32; ++k) {
                float a[4], b[8];
                #pragma unroll
                for (int j = 0; j < 4; ++j) a[j] = Xs[tr * 4 + j][k];
                float4 b0 = *reinterpret_cast<const float4*>(&Ws[k][tc * 8]);
                float4 b1 = *reinterpret_cast<const float4*>(&Ws[k][tc * 8 + 4]);
                b[0] = b0.x; b[1] = b0.y; b[2] = b0.z; b[3] = b0.w;
                b[4] = b1.x; b[5] = b1.y; b[6] = b1.z; b[7] = b1.w;
                #pragma unroll
                for (int j = 0; j < 4; ++j)
                    #pragma unroll
                    for (int jj = 0; jj < 8; ++jj)
                        acc[j][jj] = fmaf(a[j], b[jj], acc[j][jj]);
            }
        }
    }
    __syncthreads();

    // epilogue: add bias, store pre-BN, accumulate per-feature sum/sumsq
    float bias[8];
    #pragma unroll
    for (int jj = 0; jj < 8; ++jj) bias[jj] = g_bias[tc * 8 + jj];
    float scol[8], qcol[8];
    #pragma unroll
    for (int jj = 0; jj < 8; ++jj) { scol[jj] = 0.f; qcol[jj] = 0.f; }
    #pragma unroll
    for (int j = 0; j < 4; ++j) {
        int r = row0 + tr * 4 + j;
        if (r >= N_NODES) continue;
        float v[8];
        #pragma unroll
        for (int jj = 0; jj < 8; ++jj) {
            v[jj] = acc[j][jj] + bias[jj];
            scol[jj] += v[jj];
            qcol[jj] += v[jj] * v[jj];
        }
        float4* dst = reinterpret_cast<float4*>(g_pre + (size_t)r * 128 + tc * 8);
        dst[0] = make_float4(v[0], v[1], v[2], v[3]);
        dst[1] = make_float4(v[4], v[5], v[6], v[7]);
    }
    #pragma unroll
    for (int jj = 0; jj < 8; ++jj) {
        atomicAdd(&bsum[tc * 8 + jj], scol[jj]);
        atomicAdd(&bsq[tc * 8 + jj], qcol[jj]);
    }
    __syncthreads();
    if (tid < 128) {
        atomicAdd(&g_sum[tid], bsum[tid]);
        atomicAdd(&g_sumsq[tid], bsq[tid]);
    }
}

// ---------------- K4: finalize BN statistics ----------------
__global__ void stats_kernel(const float* __restrict__ gamma,
                             const float* __restrict__ beta) {
    int c = threadIdx.x;
    float inv_n = 1.f / (float)N_NODES;
    float mean = g_sum[c] * inv_n;
    float var = fmaxf(g_sumsq[c] * inv_n - mean * mean, 0.f);
    float sc = gamma[c] / sqrtf(var + BN_EPS);
    g_scale[c] = sc;
    g_shift[c] = beta[c] - mean * sc;
}

// ---------------- K5: normalize + exact GELU ----------------
__global__ __launch_bounds__(256) void final_kernel(float* __restrict__ out) {
    int i = blockIdx.x * blockDim.x + threadIdx.x;   // float4 index
    if (i >= N_NODES * OUT_F / 4) return;
    int c = (i * 4) & 127;
    float4 v = reinterpret_cast<const float4*>(g_pre)[i];
    float sc0 = g_scale[c + 0], sh0 = g_shift[c + 0];
    float sc1 = g_scale[c + 1], sh1 = g_shift[c + 1];
    float sc2 = g_scale[c + 2], sh2 = g_shift[c + 2];
    float sc3 = g_scale[c + 3], sh3 = g_shift[c + 3];
    float r;
    r = fmaf(v.x, sc0, sh0); v.x = 0.5f * r * (1.f + erff(r * 0.70710678118654752f));
    r = fmaf(v.y, sc1, sh1); v.y = 0.5f * r * (1.f + erff(r * 0.70710678118654752f));
    r = fmaf(v.z, sc2, sh2); v.z = 0.5f * r * (1.f + erff(r * 0.70710678118654752f));
    r = fmaf(v.w, sc3, sh3); v.w = 0.5f * r * (1.f + erff(r * 0.70710678118654752f));
    reinterpret_cast<float4*>(out)[i] = v;
}

// ---------------- launcher ----------------
extern "C" void kernel_launch(void* const* d_in, const int* in_sizes, int n_in,
                              void* d_out, int out_size) {
    const float* x          = (const float*)d_in[0];
    const long long* ei     = (const long long*)d_in[1];
    const float* W_fuse     = (const float*)d_in[2];
    const float* b_fuse     = (const float*)d_in[3];
    const float* W_in       = (const float*)d_in[4];
    const float* b_in       = (const float*)d_in[5];
    const float* cw         = (const float*)d_in[6];
    const float* alpha      = (const float*)d_in[7];
    const float* gamma      = (const float*)d_in[8];
    const float* beta       = (const float*)d_in[9];
    float* out              = (float*)d_out;

    zero_kernel<<<2048, 256>>>();
    detect_kernel<<<1, 32>>>(ei);
    precompute_kernel<<<128, 128>>>(W_fuse, b_fuse, W_in, b_in, cw, alpha);
    agg_kernel<<<(N_EDGES * 32) / 256, 256>>>(x, ei);
    gemm_kernel<<<(N_NODES + BM - 1) / BM, 256>>>(x);
    stats_kernel<<<1, 128>>>(gamma, beta);
    final_kernel<<<(N_NODES * OUT_F / 4 + 255) / 256, 256>>>(out);
}

// round 3
// speedup vs baseline: 1.4140x; 1.4140x over previous
#include <cuda_runtime.h>
#include <cuda_bf16.h>
#include <stdint.h>
#include <math.h>

#define N_NODES 50000
#define N_EDGES 800000
#define IN_F 128
#define OUT_F 128
#define BN_EPS 1e-5f

// ---------------- device scratch ----------------
__device__ float g_agg[N_NODES * IN_F];
__device__ float g_cnt[N_NODES];
__device__ __align__(16) __nv_bfloat16 g_Whi[OUT_F * 256];  // [Wa|Wb] hi, K-major
__device__ __align__(16) __nv_bfloat16 g_Wlo[OUT_F * 256];  // [Wa|Wb] lo
__device__ float g_bias[OUT_F];
__device__ float g_pre[N_NODES * OUT_F];
__device__ float g_sum[OUT_F];
__device__ float g_sumsq[OUT_F];
__device__ float g_scale[OUT_F];
__device__ float g_shift[OUT_F];
__device__ int   g_is64;

__device__ __forceinline__ uint32_t smem_u32(const void* p) {
    uint32_t a;
    asm("{ .reg .u64 t; cvta.to.shared.u64 t, %1; cvt.u32.u64 %0, t; }" : "=r"(a) : "l"(p));
    return a;
}
static __device__ __forceinline__ uint32_t pack2(__nv_bfloat16 a, __nv_bfloat16 b) {
    return (uint32_t)__bfloat16_as_ushort(a) | ((uint32_t)__bfloat16_as_ushort(b) << 16);
}

#define LDSM_X4(r, addr)                                                          \
    asm volatile("ldmatrix.sync.aligned.m8n8.x4.shared.b16 {%0,%1,%2,%3}, [%4];"  \
                 : "=r"((r)[0]), "=r"((r)[1]), "=r"((r)[2]), "=r"((r)[3])         \
                 : "r"(addr))
#define LDSM_X2(r, addr)                                                          \
    asm volatile("ldmatrix.sync.aligned.m8n8.x2.shared.b16 {%0,%1}, [%2];"        \
                 : "=r"((r)[0]), "=r"((r)[1]) : "r"(addr))
#define MMA_BF16(c, a, b)                                                         \
    asm volatile("mma.sync.aligned.m16n8k16.row.col.f32.bf16.bf16.f32 "           \
                 "{%0,%1,%2,%3}, {%4,%5,%6,%7}, {%8,%9}, {%0,%1,%2,%3};"          \
                 : "+f"((c)[0]), "+f"((c)[1]), "+f"((c)[2]), "+f"((c)[3])         \
                 : "r"((a)[0]), "r"((a)[1]), "r"((a)[2]), "r"((a)[3]),            \
                   "r"((b)[0]), "r"((b)[1]))

// ---------------- K0: zero scratch ----------------
__global__ void zero_kernel() {
    int i = blockIdx.x * blockDim.x + threadIdx.x;
    int stride = gridDim.x * blockDim.x;
    float4 z = make_float4(0.f, 0.f, 0.f, 0.f);
    for (int j = i; j < N_NODES * IN_F / 4; j += stride)
        reinterpret_cast<float4*>(g_agg)[j] = z;
    for (int j = i; j < N_NODES; j += stride) g_cnt[j] = 0.f;
    if (i < OUT_F) { g_sum[i] = 0.f; g_sumsq[i] = 0.f; }
}

// ---------------- K0b: detect edge_index dtype ----------------
__global__ void detect_kernel(const long long* __restrict__ ei) {
    if (threadIdx.x == 0 && blockIdx.x == 0) {
        int ok = 1;
        for (int i = 0; i < 1024; ++i) {
            long long v = ei[i];
            if (v < 0 || v >= (long long)N_NODES) { ok = 0; break; }
        }
        g_is64 = ok;
    }
}

// ---------------- K1: fold circulant into weights; emit bf16 hi/lo ----------------
__global__ void precompute_kernel(const float* __restrict__ W_fuse,
                                  const float* __restrict__ b_fuse,
                                  const float* __restrict__ W_in,
                                  const float* __restrict__ b_in,
                                  const float* __restrict__ cw,
                                  const float* __restrict__ alpha_p) {
    __shared__ float k_sh[128];
    int t = blockIdx.x;
    int i = threadIdx.x;
    {
        float acc = cw[0];
        acc += cw[128] * ((i & 1) ? -1.f : 1.f);
        for (int f = 1; f < 64; ++f) {
            float wr = cw[2 * f], wi = cw[2 * f + 1];
            int m = (f * i) & 127;
            float theta = (float)m * (6.283185307179586f / 128.f);
            float s, c;
            sincosf(theta, &s, &c);
            acc += 2.f * (wr * c - wi * s);
        }
        k_sh[i] = acc * (1.f / 128.f);
    }
    __syncthreads();
    float alpha = *alpha_p;
    float w = 0.f;
    #pragma unroll 8
    for (int s = 0; s < 128; ++s)
        w += k_sh[(t - s) & 127] * W_in[s * IN_F + i];
    float wa = W_fuse[t * (2 * IN_F) + i] + alpha * w;
    float wb = W_fuse[t * (2 * IN_F) + IN_F + i];
    __nv_bfloat16 h;
    h = __float2bfloat16(wa);
    g_Whi[t * 256 + i] = h;
    g_Wlo[t * 256 + i] = __float2bfloat16(wa - __bfloat162float(h));
    h = __float2bfloat16(wb);
    g_Whi[t * 256 + 128 + i] = h;
    g_Wlo[t * 256 + 128 + i] = __float2bfloat16(wb - __bfloat162float(h));
    if (i == 0) {
        float b = 0.f;
        for (int s = 0; s < 128; ++s) b += k_sh[(t - s) & 127] * b_in[s];
        g_bias[t] = b_fuse[t] + alpha * b;
    }
}

// ---------------- K2: scatter-sum aggregation (warp per edge) ----------------
__global__ __launch_bounds__(256) void agg_kernel(const float* __restrict__ x,
                                                  const long long* __restrict__ ei) {
    int warp = (blockIdx.x * blockDim.x + threadIdx.x) >> 5;
    int lane = threadIdx.x & 31;
    if (warp >= N_EDGES) return;
    long long src, dst;
    if (g_is64) {
        src = ei[warp];
        dst = ei[N_EDGES + warp];
    } else {
        const int* ei32 = (const int*)ei;
        src = (long long)ei32[warp];
        dst = (long long)ei32[N_EDGES + warp];
    }
    const float4* xr = reinterpret_cast<const float4*>(x + (size_t)src * IN_F);
    float4 v = xr[lane];
    float4* ar = reinterpret_cast<float4*>(g_agg + (size_t)dst * IN_F) + lane;
    asm volatile("red.global.add.v4.f32 [%0], {%1, %2, %3, %4};"
                 :: "l"(ar), "f"(v.x), "f"(v.y), "f"(v.z), "f"(v.w) : "memory");
    if (lane == 0) atomicAdd(&g_cnt[dst], 1.f);
}

// ---------------- K3: HMMA bf16 split-precision GEMM + fused BN partial stats ----
// out[128x128] = [x | agg/cnt](K=256) @ [Wa|Wb]^T via Ahi*Whi + Ahi*Wlo + Alo*Whi.
// smem: Ah,Al,Wh,Wl each 128 rows x 64 k bf16, row stride 72 (144B, LDSM-clean).
#define ROWSTR 72
#define TILE_B (128 * ROWSTR * 2)            // 18432 bytes
#define GEMM_DSMEM (4 * TILE_B)              // 73728 bytes
__global__ __launch_bounds__(256) void gemm_mma_kernel(const float* __restrict__ x) {
    extern __shared__ __align__(16) char dsm[];
    __nv_bfloat16* Ah = reinterpret_cast<__nv_bfloat16*>(dsm);
    __nv_bfloat16* Al = reinterpret_cast<__nv_bfloat16*>(dsm + TILE_B);
    __nv_bfloat16* Wh = reinterpret_cast<__nv_bfloat16*>(dsm + 2 * TILE_B);
    __nv_bfloat16* Wl = reinterpret_cast<__nv_bfloat16*>(dsm + 3 * TILE_B);

    __shared__ float s_rinv[128];
    __shared__ float s_bias[128];
    __shared__ float s_bsum[128];
    __shared__ float s_bsq[128];

    int tid = threadIdx.x;
    int wid = tid >> 5, lane = tid & 31;
    int row0 = blockIdx.x * 128;
    int wm = wid & 1;          // 0..1 -> rows wm*64
    int wn = wid >> 1;         // 0..3 -> cols wn*32

    if (tid < 128) {
        int r = row0 + tid;
        float c = (r < N_NODES) ? g_cnt[r] : 1.f;
        s_rinv[tid] = 1.f / fmaxf(c, 1.f);
        s_bias[tid] = g_bias[tid];
        s_bsum[tid] = 0.f;
        s_bsq[tid] = 0.f;
    }
    __syncthreads();

    float acc[4][4][4];
    #pragma unroll
    for (int a = 0; a < 4; ++a)
        #pragma unroll
        for (int b = 0; b < 4; ++b)
            #pragma unroll
            for (int c = 0; c < 4; ++c) acc[a][b][c] = 0.f;

    uint32_t Ah_b = smem_u32(Ah), Al_b = smem_u32(Al);
    uint32_t Wh_b = smem_u32(Wh), Wl_b = smem_u32(Wl);

    for (int kc = 0; kc < 4; ++kc) {
        const float* src = (kc < 2) ? x : g_agg;
        int koff = (kc & 1) * 64;
        bool isagg = (kc >= 2);
        if (kc) __syncthreads();
        // A chunk: 128 rows x 64 k fp32 -> bf16 hi/lo
        #pragma unroll
        for (int l = 0; l < 8; ++l) {
            int idx = tid + l * 256;
            int r = idx >> 4, seg = idx & 15;
            int gr = row0 + r;
            if (gr >= N_NODES) gr = N_NODES - 1;
            float4 v = *reinterpret_cast<const float4*>(src + (size_t)gr * 128 + koff + seg * 4);
            if (isagg) { float ri = s_rinv[r]; v.x *= ri; v.y *= ri; v.z *= ri; v.w *= ri; }
            __nv_bfloat16 h0 = __float2bfloat16(v.x), h1 = __float2bfloat16(v.y);
            __nv_bfloat16 h2 = __float2bfloat16(v.z), h3 = __float2bfloat16(v.w);
            __nv_bfloat16 l0 = __float2bfloat16(v.x - __bfloat162float(h0));
            __nv_bfloat16 l1 = __float2bfloat16(v.y - __bfloat162float(h1));
            __nv_bfloat16 l2 = __float2bfloat16(v.z - __bfloat162float(h2));
            __nv_bfloat16 l3 = __float2bfloat16(v.w - __bfloat162float(h3));
            int o = r * ROWSTR + seg * 4;
            *reinterpret_cast<uint2*>(Ah + o) = make_uint2(pack2(h0, h1), pack2(h2, h3));
            *reinterpret_cast<uint2*>(Al + o) = make_uint2(pack2(l0, l1), pack2(l2, l3));
        }
        // W chunk: 128 n x 64 k bf16 hi/lo
        #pragma unroll
        for (int l = 0; l < 4; ++l) {
            int idx = tid + l * 256;
            int n = idx >> 3, seg = idx & 7;
            uint4 vh = *reinterpret_cast<const uint4*>(g_Whi + n * 256 + kc * 64 + seg * 8);
            uint4 vl = *reinterpret_cast<const uint4*>(g_Wlo + n * 256 + kc * 64 + seg * 8);
            int o = n * ROWSTR + seg * 8;
            *reinterpret_cast<uint4*>(Wh + o) = vh;
            *reinterpret_cast<uint4*>(Wl + o) = vl;
        }
        __syncthreads();

        #pragma unroll
        for (int ks = 0; ks < 4; ++ks) {
            uint32_t ah[4][4], al[4][4], bh[4][2], bl[4][2];
            uint32_t aoff = (uint32_t)((wm * 64 + (lane & 15)) * ROWSTR + ks * 16 + (lane >> 4) * 8) * 2;
            #pragma unroll
            for (int mt = 0; mt < 4; ++mt) {
                LDSM_X4(ah[mt], Ah_b + aoff + mt * 16 * ROWSTR * 2);
                LDSM_X4(al[mt], Al_b + aoff + mt * 16 * ROWSTR * 2);
            }
            uint32_t boff = (uint32_t)((wn * 32 + (lane & 7)) * ROWSTR + ks * 16 + ((lane >> 3) & 1) * 8) * 2;
            #pragma unroll
            for (int nt = 0; nt < 4; ++nt) {
                LDSM_X2(bh[nt], Wh_b + boff + nt * 8 * ROWSTR * 2);
                LDSM_X2(bl[nt], Wl_b + boff + nt * 8 * ROWSTR * 2);
            }
            #pragma unroll
            for (int mt = 0; mt < 4; ++mt)
                #pragma unroll
                for (int nt = 0; nt < 4; ++nt) {
                    MMA_BF16(acc[mt][nt], ah[mt], bh[nt]);
                    MMA_BF16(acc[mt][nt], ah[mt], bl[nt]);
                    MMA_BF16(acc[mt][nt], al[mt], bh[nt]);
                }
        }
    }

    // epilogue: bias add, store pre-BN, fused per-column sum/sumsq
    int lr = lane >> 2;
    int lc = (lane & 3) * 2;
    float scol[8], qcol[8];
    #pragma unroll
    for (int j = 0; j < 8; ++j) { scol[j] = 0.f; qcol[j] = 0.f; }
    #pragma unroll
    for (int mt = 0; mt < 4; ++mt) {
        #pragma unroll
        for (int h = 0; h < 2; ++h) {
            int r = row0 + wm * 64 + mt * 16 + lr + h * 8;
            bool valid = (r < N_NODES);
            #pragma unroll
            for (int nt = 0; nt < 4; ++nt) {
                int col = wn * 32 + nt * 8 + lc;
                float v0 = acc[mt][nt][h * 2 + 0] + s_bias[col];
                float v1 = acc[mt][nt][h * 2 + 1] + s_bias[col + 1];
                if (valid) {
                    *reinterpret_cast<float2*>(g_pre + (size_t)r * 128 + col) = make_float2(v0, v1);
                    scol[nt * 2 + 0] += v0; qcol[nt * 2 + 0] += v0 * v0;
                    scol[nt * 2 + 1] += v1; qcol[nt * 2 + 1] += v1 * v1;
                }
            }
        }
    }
    #pragma unroll
    for (int nt = 0; nt < 4; ++nt) {
        int col = wn * 32 + nt * 8 + lc;
        atomicAdd(&s_bsum[col], scol[nt * 2 + 0]);
        atomicAdd(&s_bsq[col], qcol[nt * 2 + 0]);
        atomicAdd(&s_bsum[col + 1], scol[nt * 2 + 1]);
        atomicAdd(&s_bsq[col + 1], qcol[nt * 2 + 1]);
    }
    __syncthreads();
    if (tid < 128) {
        atomicAdd(&g_sum[tid], s_bsum[tid]);
        atomicAdd(&g_sumsq[tid], s_bsq[tid]);
    }
}

// ---------------- K4: finalize BN statistics ----------------
__global__ void stats_kernel(const float* __restrict__ gamma,
                             const float* __restrict__ beta) {
    int c = threadIdx.x;
    float inv_n = 1.f / (float)N_NODES;
    float mean = g_sum[c] * inv_n;
    float var = fmaxf(g_sumsq[c] * inv_n - mean * mean, 0.f);
    float sc = gamma[c] / sqrtf(var + BN_EPS);
    g_scale[c] = sc;
    g_shift[c] = beta[c] - mean * sc;
}

// ---------------- K5: normalize + exact GELU ----------------
__global__ __launch_bounds__(256) void final_kernel(float* __restrict__ out) {
    int i = blockIdx.x * blockDim.x + threadIdx.x;
    if (i >= N_NODES * OUT_F / 4) return;
    int c = (i * 4) & 127;
    float4 v = reinterpret_cast<const float4*>(g_pre)[i];
    float sc0 = g_scale[c + 0], sh0 = g_shift[c + 0];
    float sc1 = g_scale[c + 1], sh1 = g_shift[c + 1];
    float sc2 = g_scale[c + 2], sh2 = g_shift[c + 2];
    float sc3 = g_scale[c + 3], sh3 = g_shift[c + 3];
    float r;
    r = fmaf(v.x, sc0, sh0); v.x = 0.5f * r * (1.f + erff(r * 0.70710678118654752f));
    r = fmaf(v.y, sc1, sh1); v.y = 0.5f * r * (1.f + erff(r * 0.70710678118654752f));
    r = fmaf(v.z, sc2, sh2); v.z = 0.5f * r * (1.f + erff(r * 0.70710678118654752f));
    r = fmaf(v.w, sc3, sh3); v.w = 0.5f * r * (1.f + erff(r * 0.70710678118654752f));
    reinterpret_cast<float4*>(out)[i] = v;
}

// ---------------- launcher ----------------
extern "C" void kernel_launch(void* const* d_in, const int* in_sizes, int n_in,
                              void* d_out, int out_size) {
    const float* x      = (const float*)d_in[0];
    const long long* ei = (const long long*)d_in[1];
    const float* W_fuse = (const float*)d_in[2];
    const float* b_fuse = (const float*)d_in[3];
    const float* W_in   = (const float*)d_in[4];
    const float* b_in   = (const float*)d_in[5];
    const float* cw     = (const float*)d_in[6];
    const float* alpha  = (const float*)d_in[7];
    const float* gamma  = (const float*)d_in[8];
    const float* beta   = (const float*)d_in[9];
    float* out          = (float*)d_out;

    cudaFuncSetAttribute(gemm_mma_kernel, cudaFuncAttributeMaxDynamicSharedMemorySize, GEMM_DSMEM);

    zero_kernel<<<1024, 256>>>();
    detect_kernel<<<1, 32>>>(ei);
    precompute_kernel<<<128, 128>>>(W_fuse, b_fuse, W_in, b_in, cw, alpha);
    agg_kernel<<<(N_EDGES * 32) / 256, 256>>>(x, ei);
    gemm_mma_kernel<<<(N_NODES + 127) / 128, 256, GEMM_DSMEM>>>(x);
    stats_kernel<<<1, 128>>>(gamma, beta);
    final_kernel<<<(N_NODES * OUT_F / 4 + 255) / 256, 256>>>(out);
}

// round 4
// speedup vs baseline: 1.9493x; 1.3786x over previous
#include <cuda_runtime.h>
#include <cuda_bf16.h>
#include <stdint.h>
#include <math.h>

#define N_NODES 50000
#define N_EDGES 800000
#define IN_F 128
#define OUT_F 128
#define BN_EPS 1e-5f
#define SCAN_BLKS 49    // ceil(50000/1024)

// ---------------- device scratch ----------------
__device__ float g_agg[N_NODES * IN_F];     // mean-aggregated neighbor feats
__device__ int   g_deg[N_NODES];
__device__ int   g_start[N_NODES];
__device__ int   g_pos[N_NODES];
__device__ int   g_csr[N_EDGES];
__device__ int   g_blocksum[SCAN_BLKS];
__device__ __align__(16) __nv_bfloat16 g_Whi[OUT_F * 256];
__device__ __align__(16) __nv_bfloat16 g_Wlo[OUT_F * 256];
__device__ float g_bias[OUT_F];
__device__ float g_pre[N_NODES * OUT_F];
__device__ float g_sum[OUT_F];
__device__ float g_sumsq[OUT_F];
__device__ float g_scale[OUT_F];
__device__ float g_shift[OUT_F];
__device__ int   g_is64;

__device__ __forceinline__ uint32_t smem_u32(const void* p) {
    uint32_t a;
    asm("{ .reg .u64 t; cvta.to.shared.u64 t, %1; cvt.u32.u64 %0, t; }" : "=r"(a) : "l"(p));
    return a;
}
static __device__ __forceinline__ uint32_t pack2(__nv_bfloat16 a, __nv_bfloat16 b) {
    return (uint32_t)__bfloat16_as_ushort(a) | ((uint32_t)__bfloat16_as_ushort(b) << 16);
}

#define LDSM_X4(r, addr)                                                          \
    asm volatile("ldmatrix.sync.aligned.m8n8.x4.shared.b16 {%0,%1,%2,%3}, [%4];"  \
                 : "=r"((r)[0]), "=r"((r)[1]), "=r"((r)[2]), "=r"((r)[3])         \
                 : "r"(addr))
#define LDSM_X2(r, addr)                                                          \
    asm volatile("ldmatrix.sync.aligned.m8n8.x2.shared.b16 {%0,%1}, [%2];"        \
                 : "=r"((r)[0]), "=r"((r)[1]) : "r"(addr))
#define MMA_BF16(c, a, b)                                                         \
    asm volatile("mma.sync.aligned.m16n8k16.row.col.f32.bf16.bf16.f32 "           \
                 "{%0,%1,%2,%3}, {%4,%5,%6,%7}, {%8,%9}, {%0,%1,%2,%3};"          \
                 : "+f"((c)[0]), "+f"((c)[1]), "+f"((c)[2]), "+f"((c)[3])         \
                 : "r"((a)[0]), "r"((a)[1]), "r"((a)[2]), "r"((a)[3]),            \
                   "r"((b)[0]), "r"((b)[1]))

// ---------------- K0: zero counters + BN accumulators ----------------
__global__ void zero_kernel() {
    int i = blockIdx.x * blockDim.x + threadIdx.x;
    int stride = gridDim.x * blockDim.x;
    for (int j = i; j < N_NODES; j += stride) g_deg[j] = 0;
    if (i < OUT_F) { g_sum[i] = 0.f; g_sumsq[i] = 0.f; }
}

// ---------------- K0b: detect edge_index dtype ----------------
__global__ void detect_kernel(const long long* __restrict__ ei) {
    if (threadIdx.x == 0 && blockIdx.x == 0) {
        int ok = 1;
        for (int i = 0; i < 1024; ++i) {
            long long v = ei[i];
            if (v < 0 || v >= (long long)N_NODES) { ok = 0; break; }
        }
        g_is64 = ok;
    }
}

// ---------------- K1: fold circulant into weights; emit bf16 hi/lo ----------------
__global__ void precompute_kernel(const float* __restrict__ W_fuse,
                                  const float* __restrict__ b_fuse,
                                  const float* __restrict__ W_in,
                                  const float* __restrict__ b_in,
                                  const float* __restrict__ cw,
                                  const float* __restrict__ alpha_p) {
    __shared__ float k_sh[128];
    int t = blockIdx.x;
    int i = threadIdx.x;
    {
        float acc = cw[0];
        acc += cw[128] * ((i & 1) ? -1.f : 1.f);
        for (int f = 1; f < 64; ++f) {
            float wr = cw[2 * f], wi = cw[2 * f + 1];
            int m = (f * i) & 127;
            float theta = (float)m * (6.283185307179586f / 128.f);
            float s, c;
            sincosf(theta, &s, &c);
            acc += 2.f * (wr * c - wi * s);
        }
        k_sh[i] = acc * (1.f / 128.f);
    }
    __syncthreads();
    float alpha = *alpha_p;
    float w = 0.f;
    #pragma unroll 8
    for (int s = 0; s < 128; ++s)
        w += k_sh[(t - s) & 127] * W_in[s * IN_F + i];
    float wa = W_fuse[t * (2 * IN_F) + i] + alpha * w;
    float wb = W_fuse[t * (2 * IN_F) + IN_F + i];
    __nv_bfloat16 h;
    h = __float2bfloat16(wa);
    g_Whi[t * 256 + i] = h;
    g_Wlo[t * 256 + i] = __float2bfloat16(wa - __bfloat162float(h));
    h = __float2bfloat16(wb);
    g_Whi[t * 256 + 128 + i] = h;
    g_Wlo[t * 256 + 128 + i] = __float2bfloat16(wb - __bfloat162float(h));
    if (i == 0) {
        float b = 0.f;
        for (int s = 0; s < 128; ++s) b += k_sh[(t - s) & 127] * b_in[s];
        g_bias[t] = b_fuse[t] + alpha * b;
    }
}

// ---------------- CSR build ----------------
__device__ __forceinline__ int edge_dst(const long long* ei, int e) {
    return g_is64 ? (int)ei[N_EDGES + e] : ((const int*)ei)[N_EDGES + e];
}
__device__ __forceinline__ int edge_src(const long long* ei, int e) {
    return g_is64 ? (int)ei[e] : ((const int*)ei)[e];
}

__global__ __launch_bounds__(256) void hist_kernel(const long long* __restrict__ ei) {
    int e = blockIdx.x * blockDim.x + threadIdx.x;
    if (e >= N_EDGES) return;
    atomicAdd(&g_deg[edge_dst(ei, e)], 1);
}

__global__ __launch_bounds__(1024) void scanA_kernel() {
    __shared__ int wsum[32];
    int tid = threadIdx.x, lane = tid & 31, wid = tid >> 5;
    int i = blockIdx.x * 1024 + tid;
    int v = (i < N_NODES) ? g_deg[i] : 0;
    int s = v;
    #pragma unroll
    for (int d = 1; d < 32; d <<= 1) { int t = __shfl_up_sync(~0u, s, d); if (lane >= d) s += t; }
    if (lane == 31) wsum[wid] = s;
    __syncthreads();
    if (wid == 0) {
        int w = wsum[lane];
        #pragma unroll
        for (int d = 1; d < 32; d <<= 1) { int t = __shfl_up_sync(~0u, w, d); if (lane >= d) w += t; }
        wsum[lane] = w;
    }
    __syncthreads();
    int off = wid ? wsum[wid - 1] : 0;
    if (i < N_NODES) g_start[i] = s - v + off;         // block-local exclusive
    if (tid == 1023) g_blocksum[blockIdx.x] = wsum[31]; // block total
}

__global__ void scanB_kernel() {
    if (threadIdx.x == 0) {
        int run = 0;
        for (int i = 0; i < SCAN_BLKS; ++i) { int t = g_blocksum[i]; g_blocksum[i] = run; run += t; }
    }
}

__global__ __launch_bounds__(1024) void scanC_kernel() {
    int i = blockIdx.x * 1024 + threadIdx.x;
    if (i >= N_NODES) return;
    int s = g_start[i] + g_blocksum[blockIdx.x];
    g_start[i] = s;
    g_pos[i] = s;
}

__global__ __launch_bounds__(256) void scatter_kernel(const long long* __restrict__ ei) {
    int e = blockIdx.x * blockDim.x + threadIdx.x;
    if (e >= N_EDGES) return;
    int dst = edge_dst(ei, e);
    int src = edge_src(ei, e);
    int p = atomicAdd(&g_pos[dst], 1);
    g_csr[p] = src;
}

// ---------------- gather: warp per node, mean of neighbor rows ----------------
__global__ __launch_bounds__(256) void gather_kernel(const float* __restrict__ x) {
    int warp = (blockIdx.x * blockDim.x + threadIdx.x) >> 5;
    int lane = threadIdx.x & 31;
    if (warp >= N_NODES) return;
    int start = g_start[warp];
    int deg = g_deg[warp];
    int end = start + deg;
    float4 acc = make_float4(0.f, 0.f, 0.f, 0.f);
    int e = start;
    for (; e + 4 <= end; e += 4) {
        int s0 = __ldg(&g_csr[e + 0]);
        int s1 = __ldg(&g_csr[e + 1]);
        int s2 = __ldg(&g_csr[e + 2]);
        int s3 = __ldg(&g_csr[e + 3]);
        float4 v0 = __ldg(reinterpret_cast<const float4*>(x + (size_t)s0 * IN_F) + lane);
        float4 v1 = __ldg(reinterpret_cast<const float4*>(x + (size_t)s1 * IN_F) + lane);
        float4 v2 = __ldg(reinterpret_cast<const float4*>(x + (size_t)s2 * IN_F) + lane);
        float4 v3 = __ldg(reinterpret_cast<const float4*>(x + (size_t)s3 * IN_F) + lane);
        acc.x += v0.x + v1.x + v2.x + v3.x;
        acc.y += v0.y + v1.y + v2.y + v3.y;
        acc.z += v0.z + v1.z + v2.z + v3.z;
        acc.w += v0.w + v1.w + v2.w + v3.w;
    }
    for (; e < end; ++e) {
        int s = __ldg(&g_csr[e]);
        float4 v = __ldg(reinterpret_cast<const float4*>(x + (size_t)s * IN_F) + lane);
        acc.x += v.x; acc.y += v.y; acc.z += v.z; acc.w += v.w;
    }
    float rinv = 1.f / fmaxf((float)deg, 1.f);
    acc.x *= rinv; acc.y *= rinv; acc.z *= rinv; acc.w *= rinv;
    reinterpret_cast<float4*>(g_agg + (size_t)warp * IN_F)[lane] = acc;
}

// ---------------- K3: HMMA bf16 split-precision GEMM + fused BN partial stats ----
#define ROWSTR 72
#define TILE_B (128 * ROWSTR * 2)
#define GEMM_DSMEM (4 * TILE_B)
__global__ __launch_bounds__(256) void gemm_mma_kernel(const float* __restrict__ x) {
    extern __shared__ __align__(16) char dsm[];
    __nv_bfloat16* Ah = reinterpret_cast<__nv_bfloat16*>(dsm);
    __nv_bfloat16* Al = reinterpret_cast<__nv_bfloat16*>(dsm + TILE_B);
    __nv_bfloat16* Wh = reinterpret_cast<__nv_bfloat16*>(dsm + 2 * TILE_B);
    __nv_bfloat16* Wl = reinterpret_cast<__nv_bfloat16*>(dsm + 3 * TILE_B);

    __shared__ float s_bias[128];
    __shared__ float s_bsum[128];
    __shared__ float s_bsq[128];

    int tid = threadIdx.x;
    int wid = tid >> 5, lane = tid & 31;
    int row0 = blockIdx.x * 128;
    int wm = wid & 1;
    int wn = wid >> 1;

    if (tid < 128) {
        s_bias[tid] = g_bias[tid];
        s_bsum[tid] = 0.f;
        s_bsq[tid] = 0.f;
    }
    __syncthreads();

    float acc[4][4][4];
    #pragma unroll
    for (int a = 0; a < 4; ++a)
        #pragma unroll
        for (int b = 0; b < 4; ++b)
            #pragma unroll
            for (int c = 0; c < 4; ++c) acc[a][b][c] = 0.f;

    uint32_t Ah_b = smem_u32(Ah), Al_b = smem_u32(Al);
    uint32_t Wh_b = smem_u32(Wh), Wl_b = smem_u32(Wl);

    for (int kc = 0; kc < 4; ++kc) {
        const float* src = (kc < 2) ? x : g_agg;
        int koff = (kc & 1) * 64;
        if (kc) __syncthreads();
        #pragma unroll
        for (int l = 0; l < 8; ++l) {
            int idx = tid + l * 256;
            int r = idx >> 4, seg = idx & 15;
            int gr = row0 + r;
            if (gr >= N_NODES) gr = N_NODES - 1;
            float4 v = *reinterpret_cast<const float4*>(src + (size_t)gr * 128 + koff + seg * 4);
            __nv_bfloat16 h0 = __float2bfloat16(v.x), h1 = __float2bfloat16(v.y);
            __nv_bfloat16 h2 = __float2bfloat16(v.z), h3 = __float2bfloat16(v.w);
            __nv_bfloat16 l0 = __float2bfloat16(v.x - __bfloat162float(h0));
            __nv_bfloat16 l1 = __float2bfloat16(v.y - __bfloat162float(h1));
            __nv_bfloat16 l2 = __float2bfloat16(v.z - __bfloat162float(h2));
            __nv_bfloat16 l3 = __float2bfloat16(v.w - __bfloat162float(h3));
            int o = r * ROWSTR + seg * 4;
            *reinterpret_cast<uint2*>(Ah + o) = make_uint2(pack2(h0, h1), pack2(h2, h3));
            *reinterpret_cast<uint2*>(Al + o) = make_uint2(pack2(l0, l1), pack2(l2, l3));
        }
        #pragma unroll
        for (int l = 0; l < 4; ++l) {
            int idx = tid + l * 256;
            int n = idx >> 3, seg = idx & 7;
            uint4 vh = *reinterpret_cast<const uint4*>(g_Whi + n * 256 + kc * 64 + seg * 8);
            uint4 vl = *reinterpret_cast<const uint4*>(g_Wlo + n * 256 + kc * 64 + seg * 8);
            int o = n * ROWSTR + seg * 8;
            *reinterpret_cast<uint4*>(Wh + o) = vh;
            *reinterpret_cast<uint4*>(Wl + o) = vl;
        }
        __syncthreads();

        #pragma unroll
        for (int ks = 0; ks < 4; ++ks) {
            uint32_t ah[4][4], al[4][4], bh[4][2], bl[4][2];
            uint32_t aoff = (uint32_t)((wm * 64 + (lane & 15)) * ROWSTR + ks * 16 + (lane >> 4) * 8) * 2;
            #pragma unroll
            for (int mt = 0; mt < 4; ++mt) {
                LDSM_X4(ah[mt], Ah_b + aoff + mt * 16 * ROWSTR * 2);
                LDSM_X4(al[mt], Al_b + aoff + mt * 16 * ROWSTR * 2);
            }
            uint32_t boff = (uint32_t)((wn * 32 + (lane & 7)) * ROWSTR + ks * 16 + ((lane >> 3) & 1) * 8) * 2;
            #pragma unroll
            for (int nt = 0; nt < 4; ++nt) {
                LDSM_X2(bh[nt], Wh_b + boff + nt * 8 * ROWSTR * 2);
                LDSM_X2(bl[nt], Wl_b + boff + nt * 8 * ROWSTR * 2);
            }
            #pragma unroll
            for (int mt = 0; mt < 4; ++mt)
                #pragma unroll
                for (int nt = 0; nt < 4; ++nt) {
                    MMA_BF16(acc[mt][nt], ah[mt], bh[nt]);
                    MMA_BF16(acc[mt][nt], ah[mt], bl[nt]);
                    MMA_BF16(acc[mt][nt], al[mt], bh[nt]);
                }
        }
    }

    int lr = lane >> 2;
    int lc = (lane & 3) * 2;
    float scol[8], qcol[8];
    #pragma unroll
    for (int j = 0; j < 8; ++j) { scol[j] = 0.f; qcol[j] = 0.f; }
    #pragma unroll
    for (int mt = 0; mt < 4; ++mt) {
        #pragma unroll
        for (int h = 0; h < 2; ++h) {
            int r = row0 + wm * 64 + mt * 16 + lr + h * 8;
            bool valid = (r < N_NODES);
            #pragma unroll
            for (int nt = 0; nt < 4; ++nt) {
                int col = wn * 32 + nt * 8 + lc;
                float v0 = acc[mt][nt][h * 2 + 0] + s_bias[col];
                float v1 = acc[mt][nt][h * 2 + 1] + s_bias[col + 1];
                if (valid) {
                    *reinterpret_cast<float2*>(g_pre + (size_t)r * 128 + col) = make_float2(v0, v1);
                    scol[nt * 2 + 0] += v0; qcol[nt * 2 + 0] += v0 * v0;
                    scol[nt * 2 + 1] += v1; qcol[nt * 2 + 1] += v1 * v1;
                }
            }
        }
    }
    #pragma unroll
    for (int nt = 0; nt < 4; ++nt) {
        int col = wn * 32 + nt * 8 + lc;
        atomicAdd(&s_bsum[col], scol[nt * 2 + 0]);
        atomicAdd(&s_bsq[col], qcol[nt * 2 + 0]);
        atomicAdd(&s_bsum[col + 1], scol[nt * 2 + 1]);
        atomicAdd(&s_bsq[col + 1], qcol[nt * 2 + 1]);
    }
    __syncthreads();
    if (tid < 128) {
        atomicAdd(&g_sum[tid], s_bsum[tid]);
        atomicAdd(&g_sumsq[tid], s_bsq[tid]);
    }
}

// ---------------- K4: finalize BN statistics ----------------
__global__ void stats_kernel(const float* __restrict__ gamma,
                             const float* __restrict__ beta) {
    int c = threadIdx.x;
    float inv_n = 1.f / (float)N_NODES;
    float mean = g_sum[c] * inv_n;
    float var = fmaxf(g_sumsq[c] * inv_n - mean * mean, 0.f);
    float sc = gamma[c] / sqrtf(var + BN_EPS);
    g_scale[c] = sc;
    g_shift[c] = beta[c] - mean * sc;
}

// ---------------- K5: normalize + exact GELU ----------------
__global__ __launch_bounds__(256) void final_kernel(float* __restrict__ out) {
    int i = blockIdx.x * blockDim.x + threadIdx.x;
    if (i >= N_NODES * OUT_F / 4) return;
    int c = (i * 4) & 127;
    float4 v = reinterpret_cast<const float4*>(g_pre)[i];
    float sc0 = g_scale[c + 0], sh0 = g_shift[c + 0];
    float sc1 = g_scale[c + 1], sh1 = g_shift[c + 1];
    float sc2 = g_scale[c + 2], sh2 = g_shift[c + 2];
    float sc3 = g_scale[c + 3], sh3 = g_shift[c + 3];
    float r;
    r = fmaf(v.x, sc0, sh0); v.x = 0.5f * r * (1.f + erff(r * 0.70710678118654752f));
    r = fmaf(v.y, sc1, sh1); v.y = 0.5f * r * (1.f + erff(r * 0.70710678118654752f));
    r = fmaf(v.z, sc2, sh2); v.z = 0.5f * r * (1.f + erff(r * 0.70710678118654752f));
    r = fmaf(v.w, sc3, sh3); v.w = 0.5f * r * (1.f + erff(r * 0.70710678118654752f));
    reinterpret_cast<float4*>(out)[i] = v;
}

// ---------------- launcher ----------------
extern "C" void kernel_launch(void* const* d_in, const int* in_sizes, int n_in,
                              void* d_out, int out_size) {
    const float* x      = (const float*)d_in[0];
    const long long* ei = (const long long*)d_in[1];
    const float* W_fuse = (const float*)d_in[2];
    const float* b_fuse = (const float*)d_in[3];
    const float* W_in   = (const float*)d_in[4];
    const float* b_in   = (const float*)d_in[5];
    const float* cw     = (const float*)d_in[6];
    const float* alpha  = (const float*)d_in[7];
    const float* gamma  = (const float*)d_in[8];
    const float* beta   = (const float*)d_in[9];
    float* out          = (float*)d_out;

    cudaFuncSetAttribute(gemm_mma_kernel, cudaFuncAttributeMaxDynamicSharedMemorySize, GEMM_DSMEM);

    zero_kernel<<<256, 256>>>();
    detect_kernel<<<1, 32>>>(ei);
    precompute_kernel<<<128, 128>>>(W_fuse, b_fuse, W_in, b_in, cw, alpha);
    hist_kernel<<<(N_EDGES + 255) / 256, 256>>>(ei);
    scanA_kernel<<<SCAN_BLKS, 1024>>>();
    scanB_kernel<<<1, 32>>>();
    scanC_kernel<<<SCAN_BLKS, 1024>>>();
    scatter_kernel<<<(N_EDGES + 255) / 256, 256>>>(ei);
    gather_kernel<<<(N_NODES * 32 + 255) / 256, 256>>>(x);
    gemm_mma_kernel<<<(N_NODES + 127) / 128, 256, GEMM_DSMEM>>>(x);
    stats_kernel<<<1, 128>>>(gamma, beta);
    final_kernel<<<(N_NODES * OUT_F / 4 + 255) / 256, 256>>>(out);
}